// round 1
// baseline (speedup 1.0000x reference)
#include <cuda_runtime.h>
#include <math.h>

// Problem constants
#define BATCH 8
#define H 1024
#define W 1024
#define NWIN 5

// radii for windows {7,15,31,63,127}
__device__ __constant__ int c_radii[NWIN] = {3, 7, 15, 31, 63};

// Scratch: horizontal window sums (sum x, sum x^2) per window.
// Layout: [win][b][y][x] as float2  -> 5*8*1024*1024*8B = 320 MiB
__device__ float2 g_hsums[(size_t)NWIN * BATCH * H * W];

// ---------------------------------------------------------------------------
// Pass A: per-row inclusive prefix of (x, x^2) in shared memory, then emit the
// 5 horizontal clipped-window sums per pixel.
// One block per (row, batch). 1024 threads, one per pixel.
// ---------------------------------------------------------------------------
__global__ __launch_bounds__(1024) void hpass_kernel(const float* __restrict__ x,
                                                     float2* __restrict__ hsums) {
    const int y = blockIdx.x;
    const int b = blockIdx.y;
    const int t = threadIdx.x;

    __shared__ float2 bufA[W];
    __shared__ float2 bufB[W];

    const float v = x[((size_t)b * H + y) * W + t];
    bufA[t] = make_float2(v, v * v);
    __syncthreads();

    // Hillis-Steele inclusive scan (log2(1024)=10 steps), ping-pong buffers.
    float2* src = bufA;
    float2* dst = bufB;
#pragma unroll
    for (int off = 1; off < W; off <<= 1) {
        float2 s = src[t];
        if (t >= off) {
            float2 p = src[t - off];
            s.x += p.x;
            s.y += p.y;
        }
        dst[t] = s;
        __syncthreads();
        float2* tmp = src; src = dst; dst = tmp;
    }
    // src now holds inclusive prefix P[i] = sum_{0..i}

#pragma unroll
    for (int w = 0; w < NWIN; w++) {
        const int r = c_radii[w];
        const int lo = max(t - r, 0);
        const int hi = min(t + r, W - 1);
        float2 s = src[hi];
        if (lo > 0) {
            float2 p = src[lo - 1];
            s.x -= p.x;
            s.y -= p.y;
        }
        hsums[((((size_t)w * BATCH + b) * H + y) * W) + t] = s;
    }
}

// ---------------------------------------------------------------------------
// Pass B: vertical sliding window over the horizontal sums + Sauvola epilogue.
// Thread = (win, b, x, ychunk). Running fp32 sums; subtract-stream re-reads
// hit L2 (lag <= 126 rows * 4KB/block).
// grid: x = 4 xblocks * YCHUNKS, y = BATCH, z = NWIN ; block = 256 threads.
// ---------------------------------------------------------------------------
#define XBLOCKS (W / 256)
#define YCHUNKS 4
#define YCHUNK (H / YCHUNKS)

__global__ __launch_bounds__(256) void vpass_kernel(const float2* __restrict__ hsums,
                                                    const float* __restrict__ kk,
                                                    const float* __restrict__ RR,
                                                    float* __restrict__ out) {
    const int xblk = blockIdx.x & (XBLOCKS - 1);
    const int ychunk = blockIdx.x / XBLOCKS;
    const int b = blockIdx.y;
    const int w = blockIdx.z;

    const int x = xblk * 256 + threadIdx.x;
    const int r = c_radii[w];
    const float kw = kk[w];
    const float Rw = RR[w];

    const float2* col = hsums + (((size_t)w * BATCH + b) * H) * W + x;
    float* o = out + (((size_t)b * NWIN + w) * H) * W + x;

    const float cnth = (float)(min(x + r, W - 1) - max(x - r, 0) + 1);

    const int y0 = ychunk * YCHUNK;
    const int y1 = y0 + YCHUNK;

    // Prime: invariant entering iteration y is S = sum rows [y-r, y+r-1] clipped.
    float sx = 0.0f, sy = 0.0f;
    const int plo = max(y0 - r, 0);
    const int phi = min(y0 + r, H);
    for (int yy = plo; yy < phi; yy++) {
        float2 v = col[(size_t)yy * W];
        sx += v.x;
        sy += v.y;
    }

#pragma unroll 4
    for (int y = y0; y < y1; y++) {
        if (y + r < H) {
            float2 v = col[(size_t)(y + r) * W];
            sx += v.x;
            sy += v.y;
        }
        const float cntv = (float)(min(y + r, H - 1) - max(y - r, 0) + 1);
        const float inv = __frcp_rn(cnth * cntv);
        const float mean = sx * inv;
        const float m2 = sy * inv;
        const float var = fmaxf(m2 - mean * mean, 1e-6f);
        const float dev = sqrtf(var);
        o[(size_t)y * W] = mean * (1.0f + kw * (dev / Rw - 1.0f));
        if (y - r >= 0) {
            float2 v = col[(size_t)(y - r) * W];
            sx -= v.x;
            sy -= v.y;
        }
    }
}

extern "C" void kernel_launch(void* const* d_in, const int* in_sizes, int n_in,
                              void* d_out, int out_size) {
    const float* x = (const float*)d_in[0];
    const float* k = (const float*)d_in[1];
    const float* R = (const float*)d_in[2];
    float* out = (float*)d_out;

    float2* hsums;
    cudaGetSymbolAddress((void**)&hsums, g_hsums);

    dim3 gridA(H, BATCH);
    hpass_kernel<<<gridA, 1024>>>(x, hsums);

    dim3 gridB(XBLOCKS * YCHUNKS, BATCH, NWIN);
    vpass_kernel<<<gridB, 256>>>(hsums, k, R, out);
}

// round 2
// speedup vs baseline: 1.5470x; 1.5470x over previous
#include <cuda_runtime.h>
#include <cuda_fp16.h>
#include <math.h>

#define BATCH 8
#define H 1024
#define W 1024
#define NWIN 5
#define PADY 64
#define ROWS (H + 2 * PADY)   // 1152 rows per (win,batch) image in scratch
#define NIMG (NWIN * BATCH)   // 40

__device__ __constant__ int c_radii[NWIN] = {3, 7, 15, 31, 63};

// Scratch: horizontal window sums (sum x, sum x^2) packed as half2, with
// PADY zero rows above and below each image so the vertical pass needs no
// bounds checks. 40 * 1152 * 1024 * 4B = 188 M!iB.
__device__ __half2 g_hsums[(size_t)NIMG * ROWS * W];

// ---------------------------------------------------------------------------
// Zero the pad rows (must run each launch before vpass; hpass only writes
// the H real rows).
// ---------------------------------------------------------------------------
__global__ __launch_bounds__(256) void padzero_kernel(__half2* __restrict__ hs) {
    const int total = NIMG * 2 * PADY * W;
    int idx = blockIdx.x * 256 + threadIdx.x;
    if (idx >= total) return;
    int img = idx / (2 * PADY * W);
    int rem = idx - img * (2 * PADY * W);
    int rr = rem / W;
    int cc = rem - rr * W;
    int row = (rr < PADY) ? rr : (H + rr);   // bottom pads: H+PADY .. ROWS-1
    hs[((size_t)img * ROWS + row) * W + cc] = __floats2half2_rn(0.0f, 0.0f);
}

// ---------------------------------------------------------------------------
// Pass A: per-row inclusive prefix of (x, x^2) via warp shuffles + one block
// combine, then emit the 5 horizontal clipped-window sums as half2.
// One block per (row, batch). 1024 threads.
// ---------------------------------------------------------------------------
__global__ __launch_bounds__(1024) void hpass_kernel(const float* __restrict__ x,
                                                     __half2* __restrict__ hsums) {
    const int y = blockIdx.x;
    const int b = blockIdx.y;
    const int t = threadIdx.x;
    const int lane = t & 31;
    const int wid = t >> 5;

    __shared__ float2 s_warp[32];
    __shared__ float2 s_pref[W];

    const float v = x[((size_t)b * H + y) * W + t];
    float sx = v, sy = v * v;

    // warp-level inclusive scan
#pragma unroll
    for (int off = 1; off < 32; off <<= 1) {
        float ax = __shfl_up_sync(0xffffffffu, sx, off);
        float ay = __shfl_up_sync(0xffffffffu, sy, off);
        if (lane >= off) { sx += ax; sy += ay; }
    }
    if (lane == 31) s_warp[wid] = make_float2(sx, sy);
    __syncthreads();
    if (wid == 0) {
        float2 w2 = s_warp[lane];
        float wx = w2.x, wy = w2.y;
#pragma unroll
        for (int off = 1; off < 32; off <<= 1) {
            float ax = __shfl_up_sync(0xffffffffu, wx, off);
            float ay = __shfl_up_sync(0xffffffffu, wy, off);
            if (lane >= off) { wx += ax; wy += ay; }
        }
        s_warp[lane] = make_float2(wx, wy);
    }
    __syncthreads();
    if (wid > 0) {
        float2 base = s_warp[wid - 1];
        sx += base.x; sy += base.y;
    }
    s_pref[t] = make_float2(sx, sy);
    __syncthreads();

#pragma unroll
    for (int w = 0; w < NWIN; w++) {
        const int r = c_radii[w];
        const int lo = max(t - r, 0);
        const int hi = min(t + r, W - 1);
        float2 s = s_pref[hi];
        if (lo > 0) {
            float2 p = s_pref[lo - 1];
            s.x -= p.x; s.y -= p.y;
        }
        hsums[((size_t)(w * BATCH + b) * ROWS + PADY + y) * W + t] =
            __floats2half2_rn(s.x, s.y);
    }
}

// ---------------------------------------------------------------------------
// Pass B: vertical sliding window + Sauvola epilogue.
// Each thread owns 2 adjacent columns (one 8B uint2 load per row-step per
// stream). No conditionals in the loop (pad rows are zero).
// grid.x = XB2 * YCHUNKS, grid.y = BATCH, grid.z = NWIN; 256 threads.
// ---------------------------------------------------------------------------
#define XB2 (W / 512)     // 2 blocks cover 1024 cols at 2 cols/thread
#define YCHUNKS 8
#define YCHUNK (H / YCHUNKS)

__global__ __launch_bounds__(256) void vpass_kernel(const __half2* __restrict__ hsums,
                                                    const float* __restrict__ kk,
                                                    const float* __restrict__ RR,
                                                    float* __restrict__ out) {
    const int xblk = blockIdx.x & (XB2 - 1);
    const int ychunk = blockIdx.x / XB2;
    const int b = blockIdx.y;
    const int w = blockIdx.z;

    const int tx = xblk * 256 + threadIdx.x;   // 0..511
    const int x0 = 2 * tx;
    const int x1 = x0 + 1;
    const int r = c_radii[w];
    const float kw = kk[w];
    const float invR = __frcp_rn(RR[w]);

    // uint2 view: one load = 2 half2 pixels. Row stride in uint2 = W/2.
    const uint2* col = reinterpret_cast<const uint2*>(
        hsums + ((size_t)(w * BATCH + b) * ROWS + PADY) * W) + tx;
    float* o = out + (((size_t)b * NWIN + w) * H) * W + x0;

    const float cnth0 = (float)(min(x0 + r, W - 1) - max(x0 - r, 0) + 1);
    const float cnth1 = (float)(min(x1 + r, W - 1) - max(x1 - r, 0) + 1);

    const int y0 = ychunk * YCHUNK;

    float sx0 = 0.f, sy0 = 0.f, sx1 = 0.f, sy1 = 0.f;

    // Prime: S = sum of rows [y0-r, y0+r) (pad rows are zero, no clamping).
#pragma unroll 4
    for (int yy = y0 - r; yy < y0 + r; yy++) {
        uint2 u = col[(size_t)yy * (W / 2)];
        float2 f0 = __half22float2(*reinterpret_cast<__half2*>(&u.x));
        float2 f1 = __half22float2(*reinterpret_cast<__half2*>(&u.y));
        sx0 += f0.x; sy0 += f0.y; sx1 += f1.x; sy1 += f1.y;
    }

#pragma unroll 4
    for (int y = y0; y < y0 + YCHUNK; y++) {
        {   // add row y+r
            uint2 u = col[(size_t)(y + r) * (W / 2)];
            float2 f0 = __half22float2(*reinterpret_cast<__half2*>(&u.x));
            float2 f1 = __half22float2(*reinterpret_cast<__half2*>(&u.y));
            sx0 += f0.x; sy0 += f0.y; sx1 += f1.x; sy1 += f1.y;
        }
        const float cntv = (float)(min(y + r, H - 1) - max(y - r, 0) + 1);
        {
            const float inv0 = __frcp_rn(cnth0 * cntv);
            const float inv1 = __frcp_rn(cnth1 * cntv);
            const float mean0 = sx0 * inv0, m20 = sy0 * inv0;
            const float mean1 = sx1 * inv1, m21 = sy1 * inv1;
            const float dev0 = sqrtf(fmaxf(fmaf(-mean0, mean0, m20), 1e-6f));
            const float dev1 = sqrtf(fmaxf(fmaf(-mean1, mean1, m21), 1e-6f));
            float2 res;
            res.x = mean0 * fmaf(kw, fmaf(dev0, invR, -1.0f), 1.0f);
            res.y = mean1 * fmaf(kw, fmaf(dev1, invR, -1.0f), 1.0f);
            *reinterpret_cast<float2*>(o + (size_t)y * W) = res;
        }
        {   // subtract row y-r (pads are zero → harmless before y=r)
            uint2 u = col[(size_t)(y - r) * (W / 2)];
            float2 f0 = __half22float2(*reinterpret_cast<__half2*>(&u.x));
            float2 f1 = __half22float2(*reinterpret_cast<__half2*>(&u.y));
            sx0 -= f0.x; sy0 -= f0.y; sx1 -= f1.x; sy1 -= f1.y;
        }
    }
}

extern "C" void kernel_launch(void* const* d_in, const int* in_sizes, int n_in,
                              void* d_out, int out_size) {
    const float* x = (const float*)d_in[0];
    const float* k = (const float*)d_in[1];
    const float* R = (const float*)d_in[2];
    float* out = (float*)d_out;

    __half2* hsums;
    cudaGetSymbolAddress((void**)&hsums, g_hsums);

    const int pad_total = NIMG * 2 * PADY * W;
    padzero_kernel<<<(pad_total + 255) / 256, 256>>>(hsums);

    dim3 gridA(H, BATCH);
    hpass_kernel<<<gridA, 1024>>>(x, hsums);

    dim3 gridB(XB2 * YCHUNKS, BATCH, NWIN);
    vpass_kernel<<<gridB, 256>>>(hsums, k, R, out);
}